// round 3
// baseline (speedup 1.0000x reference)
#include <cuda_runtime.h>
#include <math.h>
#include <stdint.h>

// Problem constants
#define BSZ 2
#define SEQ 2048
#define EMB 2048
#define NH  16
#define NKV 4
#define DH  128
#define GQ  4
#define MTOT (BSZ*SEQ)          // 4096 rows
#define KVDIM (NKV*DH)          // 512
#define ATT_SCALE 0.08838834764831845f  // 1/sqrt(128)

// Scratch (allocation-free rule: __device__ globals)
__device__ __align__(16) float g_Q[MTOT*EMB];    // 32 MB
__device__ __align__(16) float g_K[MTOT*KVDIM];  //  8 MB
__device__ __align__(16) float g_V[MTOT*KVDIM];  //  8 MB
__device__ __align__(16) float g_O[MTOT*EMB];    // 32 MB

__device__ __forceinline__ uint32_t f2tf32(float x) {
    uint32_t r;
    asm("cvt.rna.tf32.f32 %0, %1;" : "=r"(r) : "f"(x));
    return r;
}

__device__ __forceinline__ void mma_tf32(float c[4],
                                         uint32_t a0, uint32_t a1, uint32_t a2, uint32_t a3,
                                         uint32_t b0, uint32_t b1) {
    asm volatile(
        "mma.sync.aligned.m16n8k8.row.col.f32.tf32.tf32.f32 "
        "{%0,%1,%2,%3}, {%4,%5,%6,%7}, {%8,%9}, {%0,%1,%2,%3};"
        : "+f"(c[0]), "+f"(c[1]), "+f"(c[2]), "+f"(c[3])
        : "r"(a0), "r"(a1), "r"(a2), "r"(a3), "r"(b0), "r"(b1));
}

// ---------------------------------------------------------------------------
// TF32 GEMM: C[M,N] = A[M,K] @ W[N,K]^T
// 128x128 block tile, BK=32, 256 threads (8 warps, 2x4), warp tile 64x32.
// Fragments loaded directly from smem (pad 36 -> conflict-free frag loads).
// ---------------------------------------------------------------------------
#define GPAD 36
__global__ __launch_bounds__(256, 2)
void gemm_tf32(const float* __restrict__ A, const float* __restrict__ W,
               float* __restrict__ C, int M, int N, int K) {
    __shared__ uint32_t As[128 * GPAD];
    __shared__ uint32_t Ws[128 * GPAD];

    const int tid = threadIdx.x;
    const int lane = tid & 31;
    const int wrp = tid >> 5;
    const int g = lane >> 2;   // 0..7
    const int q = lane & 3;    // 0..3
    const int wm = wrp >> 2;   // 0..1
    const int wn = wrp & 3;    // 0..3
    const int bm = blockIdx.y * 128;
    const int bn = blockIdx.x * 128;

    float acc[4][4][4];
#pragma unroll
    for (int mt = 0; mt < 4; mt++)
#pragma unroll
        for (int nt = 0; nt < 4; nt++)
#pragma unroll
            for (int e = 0; e < 4; e++) acc[mt][nt][e] = 0.f;

    // loader: 4 float4 per matrix per k-chunk.  idx = tid + 256*i
    // row = idx>>3 (0..127), kc = (idx&7)*4 (0..28)
    float4 ra[4], rw[4];
    {
#pragma unroll
        for (int i = 0; i < 4; i++) {
            const int idx = tid + 256 * i;
            const int row = idx >> 3;
            const int kc = (idx & 7) * 4;
            ra[i] = *(const float4*)&A[(size_t)(bm + row) * K + kc];
            rw[i] = *(const float4*)&W[(size_t)(bn + row) * K + kc];
        }
    }

    for (int k0 = 0; k0 < K; k0 += 32) {
        __syncthreads();   // previous compute done before smem overwrite
#pragma unroll
        for (int i = 0; i < 4; i++) {
            const int idx = tid + 256 * i;
            const int row = idx >> 3;
            const int kc = (idx & 7) * 4;
            As[row * GPAD + kc + 0] = f2tf32(ra[i].x);
            As[row * GPAD + kc + 1] = f2tf32(ra[i].y);
            As[row * GPAD + kc + 2] = f2tf32(ra[i].z);
            As[row * GPAD + kc + 3] = f2tf32(ra[i].w);
            Ws[row * GPAD + kc + 0] = f2tf32(rw[i].x);
            Ws[row * GPAD + kc + 1] = f2tf32(rw[i].y);
            Ws[row * GPAD + kc + 2] = f2tf32(rw[i].z);
            Ws[row * GPAD + kc + 3] = f2tf32(rw[i].w);
        }
        __syncthreads();

        if (k0 + 32 < K) {
            const int kn = k0 + 32;
#pragma unroll
            for (int i = 0; i < 4; i++) {
                const int idx = tid + 256 * i;
                const int row = idx >> 3;
                const int kc = (idx & 7) * 4;
                ra[i] = *(const float4*)&A[(size_t)(bm + row) * K + kn + kc];
                rw[i] = *(const float4*)&W[(size_t)(bn + row) * K + kn + kc];
            }
        }

#pragma unroll
        for (int ks = 0; ks < 4; ks++) {
            const int kb = ks * 8;
            uint32_t bf[4][2];
#pragma unroll
            for (int nt = 0; nt < 4; nt++) {
                const int n = wn * 32 + nt * 8 + g;
                bf[nt][0] = Ws[n * GPAD + kb + q];
                bf[nt][1] = Ws[n * GPAD + kb + q + 4];
            }
#pragma unroll
            for (int mt = 0; mt < 4; mt++) {
                const int row = wm * 64 + mt * 16 + g;
                uint32_t a0 = As[row * GPAD + kb + q];
                uint32_t a1 = As[(row + 8) * GPAD + kb + q];
                uint32_t a2 = As[row * GPAD + kb + q + 4];
                uint32_t a3 = As[(row + 8) * GPAD + kb + q + 4];
#pragma unroll
                for (int nt = 0; nt < 4; nt++)
                    mma_tf32(acc[mt][nt], a0, a1, a2, a3, bf[nt][0], bf[nt][1]);
            }
        }
    }

    // epilogue
#pragma unroll
    for (int mt = 0; mt < 4; mt++) {
        const int row = bm + wm * 64 + mt * 16 + g;
#pragma unroll
        for (int nt = 0; nt < 4; nt++) {
            const int col = bn + wn * 32 + nt * 8 + 2 * q;
            float2 v0 = make_float2(acc[mt][nt][0], acc[mt][nt][1]);
            float2 v1 = make_float2(acc[mt][nt][2], acc[mt][nt][3]);
            *(float2*)&C[(size_t)row * N + col] = v0;
            *(float2*)&C[(size_t)(row + 8) * N + col] = v1;
        }
    }
}

// ---------------------------------------------------------------------------
// Flash attention (causal, GQA) with tf32 mma.
// Block: 256 threads (8 warps), q-tile 128 (16 rows/warp), k-tile 64.
// Q lives in A-fragments in registers; K/V row-major in smem;
// P staged in per-warp-private smem region (no block sync needed for P).
// ---------------------------------------------------------------------------
#define KVPAD 132
#define PPAD  68
#define SM_KS 0
#define SM_VS (64 * KVPAD)
#define SM_PS (2 * 64 * KVPAD)
#define ATTN_SMEM_U32 (2 * 64 * KVPAD + 128 * PPAD)
#define ATTN_SMEM_BYTES (ATTN_SMEM_U32 * 4)

__global__ __launch_bounds__(256, 1)
void attn_tf32(const float* __restrict__ Q, const float* __restrict__ K,
               const float* __restrict__ V, float* __restrict__ O) {
    const int qt = (gridDim.x - 1) - blockIdx.x;  // reversed: big tiles first
    const int h  = blockIdx.y;
    const int b  = blockIdx.z;
    const int kvh = h / GQ;

    extern __shared__ uint32_t smu[];
    uint32_t* Ks = smu + SM_KS;   // [64][132] (row=kcol, col=d)
    uint32_t* Vs = smu + SM_VS;   // [64][132]
    uint32_t* Ps = smu + SM_PS;   // [128][68] (row=qrow-in-tile, col=kcol)

    const int tid = threadIdx.x;
    const int lane = tid & 31;
    const int w = tid >> 5;       // warp 0..7
    const int g = lane >> 2;
    const int q = lane & 3;

    const int qrow0 = b * SEQ + qt * 128;

    // Q fragments: 16 k-tiles over d=128, held in registers
    uint32_t qa[16][4];
    {
        const float* qb = Q + (size_t)(qrow0 + w * 16) * EMB + h * DH;
#pragma unroll
        for (int kt16 = 0; kt16 < 16; kt16++) {
            const int d0 = kt16 * 8;
            qa[kt16][0] = f2tf32(qb[(size_t)g * EMB + d0 + q]);
            qa[kt16][1] = f2tf32(qb[(size_t)(g + 8) * EMB + d0 + q]);
            qa[kt16][2] = f2tf32(qb[(size_t)g * EMB + d0 + q + 4]);
            qa[kt16][3] = f2tf32(qb[(size_t)(g + 8) * EMB + d0 + q + 4]);
        }
    }

    float o[16][4];
#pragma unroll
    for (int nt = 0; nt < 16; nt++)
#pragma unroll
        for (int e = 0; e < 4; e++) o[nt][e] = 0.f;

    float m0 = -INFINITY, m1 = -INFINITY, l0 = 0.f, l1 = 0.f;

    const int qg0 = qt * 128 + w * 16 + g;   // global q index for rows (c0,c1)
    const int qg1 = qg0 + 8;

    const int nkt = 2 * qt + 2;
    for (int kt = 0; kt < nkt; kt++) {
        // ---- load K/V tile (64 rows x 128 d) ----
        __syncthreads();   // previous PV done reading Vs
        {
            const float* kb = K + (size_t)(b * SEQ + kt * 64) * KVDIM + kvh * DH;
            const float* vb = V + (size_t)(b * SEQ + kt * 64) * KVDIM + kvh * DH;
#pragma unroll
            for (int i = 0; i < 8; i++) {
                const int idx = tid + 256 * i;      // 0..2047
                const int row = idx >> 5;           // 0..63
                const int dc = (idx & 31) * 4;      // 0..124
                float4 kv = *(const float4*)&kb[(size_t)row * KVDIM + dc];
                float4 vv = *(const float4*)&vb[(size_t)row * KVDIM + dc];
                Ks[row * KVPAD + dc + 0] = f2tf32(kv.x);
                Ks[row * KVPAD + dc + 1] = f2tf32(kv.y);
                Ks[row * KVPAD + dc + 2] = f2tf32(kv.z);
                Ks[row * KVPAD + dc + 3] = f2tf32(kv.w);
                Vs[row * KVPAD + dc + 0] = f2tf32(vv.x);
                Vs[row * KVPAD + dc + 1] = f2tf32(vv.y);
                Vs[row * KVPAD + dc + 2] = f2tf32(vv.z);
                Vs[row * KVPAD + dc + 3] = f2tf32(vv.w);
            }
        }
        __syncthreads();

        // ---- S = Q @ K^T (16 rows x 64 cols per warp) ----
        float s[8][4];
#pragma unroll
        for (int nt = 0; nt < 8; nt++)
#pragma unroll
            for (int e = 0; e < 4; e++) s[nt][e] = 0.f;

#pragma unroll
        for (int ks = 0; ks < 16; ks++) {
            const int kd = ks * 8;
#pragma unroll
            for (int nt = 0; nt < 8; nt++) {
                uint32_t b0 = Ks[(nt * 8 + g) * KVPAD + kd + q];
                uint32_t b1 = Ks[(nt * 8 + g) * KVPAD + kd + q + 4];
                mma_tf32(s[nt], qa[ks][0], qa[ks][1], qa[ks][2], qa[ks][3], b0, b1);
            }
        }

        // ---- scale + causal mask ----
#pragma unroll
        for (int nt = 0; nt < 8; nt++) {
            const int kg = kt * 64 + nt * 8 + 2 * q;
            s[nt][0] = (kg     > qg0) ? -INFINITY : s[nt][0] * ATT_SCALE;
            s[nt][1] = (kg + 1 > qg0) ? -INFINITY : s[nt][1] * ATT_SCALE;
            s[nt][2] = (kg     > qg1) ? -INFINITY : s[nt][2] * ATT_SCALE;
            s[nt][3] = (kg + 1 > qg1) ? -INFINITY : s[nt][3] * ATT_SCALE;
        }

        // ---- online softmax ----
        float rm0 = -INFINITY, rm1 = -INFINITY;
#pragma unroll
        for (int nt = 0; nt < 8; nt++) {
            rm0 = fmaxf(rm0, fmaxf(s[nt][0], s[nt][1]));
            rm1 = fmaxf(rm1, fmaxf(s[nt][2], s[nt][3]));
        }
        rm0 = fmaxf(rm0, __shfl_xor_sync(0xffffffffu, rm0, 1));
        rm0 = fmaxf(rm0, __shfl_xor_sync(0xffffffffu, rm0, 2));
        rm1 = fmaxf(rm1, __shfl_xor_sync(0xffffffffu, rm1, 1));
        rm1 = fmaxf(rm1, __shfl_xor_sync(0xffffffffu, rm1, 2));

        const float mn0 = fmaxf(m0, rm0);
        const float mn1 = fmaxf(m1, rm1);
        const float c0 = __expf(m0 - mn0);
        const float c1 = __expf(m1 - mn1);
        m0 = mn0; m1 = mn1;

        float rs0 = 0.f, rs1 = 0.f;
        uint32_t* pw0 = Ps + (size_t)(w * 16 + g) * PPAD;
        uint32_t* pw1 = Ps + (size_t)(w * 16 + g + 8) * PPAD;
#pragma unroll
        for (int nt = 0; nt < 8; nt++) {
            const float p00 = __expf(s[nt][0] - mn0);
            const float p01 = __expf(s[nt][1] - mn0);
            const float p10 = __expf(s[nt][2] - mn1);
            const float p11 = __expf(s[nt][3] - mn1);
            rs0 += p00 + p01;
            rs1 += p10 + p11;
            const int cc = nt * 8 + 2 * q;
            pw0[cc] = f2tf32(p00); pw0[cc + 1] = f2tf32(p01);
            pw1[cc] = f2tf32(p10); pw1[cc + 1] = f2tf32(p11);
        }
        rs0 += __shfl_xor_sync(0xffffffffu, rs0, 1);
        rs0 += __shfl_xor_sync(0xffffffffu, rs0, 2);
        rs1 += __shfl_xor_sync(0xffffffffu, rs1, 1);
        rs1 += __shfl_xor_sync(0xffffffffu, rs1, 2);
        l0 = l0 * c0 + rs0;
        l1 = l1 * c1 + rs1;

#pragma unroll
        for (int nt = 0; nt < 16; nt++) {
            o[nt][0] *= c0; o[nt][1] *= c0;
            o[nt][2] *= c1; o[nt][3] *= c1;
        }

        __syncwarp();   // P visible within warp (P region is warp-private)

        // ---- O += P @ V ----
#pragma unroll
        for (int ks = 0; ks < 8; ks++) {
            const int kc = ks * 8;
            uint32_t a0 = Ps[(w * 16 + g) * PPAD + kc + q];
            uint32_t a1 = Ps[(w * 16 + g + 8) * PPAD + kc + q];
            uint32_t a2 = Ps[(w * 16 + g) * PPAD + kc + q + 4];
            uint32_t a3 = Ps[(w * 16 + g + 8) * PPAD + kc + q + 4];
#pragma unroll
            for (int nt = 0; nt < 16; nt++) {
                uint32_t b0 = Vs[(kc + q) * KVPAD + nt * 8 + g];
                uint32_t b1 = Vs[(kc + q + 4) * KVPAD + nt * 8 + g];
                mma_tf32(o[nt], a0, a1, a2, a3, b0, b1);
            }
        }
    }

    // ---- epilogue ----
    const float inv0 = 1.f / l0;
    const float inv1 = 1.f / l1;
    float* ob = O + (size_t)(qrow0 + w * 16) * EMB + h * DH;
#pragma unroll
    for (int nt = 0; nt < 16; nt++) {
        const int d = nt * 8 + 2 * q;
        float2 v0 = make_float2(o[nt][0] * inv0, o[nt][1] * inv0);
        float2 v1 = make_float2(o[nt][2] * inv1, o[nt][3] * inv1);
        *(float2*)&ob[(size_t)g * EMB + d] = v0;
        *(float2*)&ob[(size_t)(g + 8) * EMB + d] = v1;
    }
}

// ---------------------------------------------------------------------------
extern "C" void kernel_launch(void* const* d_in, const int* in_sizes, int n_in,
                              void* d_out, int out_size) {
    const float* x  = (const float*)d_in[0];
    const float* Wq = (const float*)d_in[1];
    const float* Wk = (const float*)d_in[2];
    const float* Wv = (const float*)d_in[3];
    const float* Wo = (const float*)d_in[4];
    float* out = (float*)d_out;

    void *pQ, *pK, *pV, *pO;
    cudaGetSymbolAddress(&pQ, g_Q);
    cudaGetSymbolAddress(&pK, g_K);
    cudaGetSymbolAddress(&pV, g_V);
    cudaGetSymbolAddress(&pO, g_O);

    cudaFuncSetAttribute(attn_tf32, cudaFuncAttributeMaxDynamicSharedMemorySize,
                         ATTN_SMEM_BYTES);

    dim3 blk(256);

    // Projections
    gemm_tf32<<<dim3(EMB / 128, MTOT / 128), blk>>>(x, Wq, (float*)pQ, MTOT, EMB, EMB);
    gemm_tf32<<<dim3(KVDIM / 128, MTOT / 128), blk>>>(x, Wk, (float*)pK, MTOT, KVDIM, EMB);
    gemm_tf32<<<dim3(KVDIM / 128, MTOT / 128), blk>>>(x, Wv, (float*)pV, MTOT, KVDIM, EMB);

    // Attention
    attn_tf32<<<dim3(SEQ / 128, NH, BSZ), blk, ATTN_SMEM_BYTES>>>(
        (const float*)pQ, (const float*)pK, (const float*)pV, (float*)pO);

    // Output projection
    gemm_tf32<<<dim3(EMB / 128, MTOT / 128), blk>>>((const float*)pO, Wo, out, MTOT, EMB, EMB);
}

// round 4
// speedup vs baseline: 2.0695x; 2.0695x over previous
#include <cuda_runtime.h>
#include <cuda_fp16.h>
#include <math.h>
#include <stdint.h>

#define BSZ 2
#define SEQ 2048
#define EMB 2048
#define NH  16
#define NKV 4
#define DH  128
#define MTOT (BSZ*SEQ)
#define KVDIM (NKV*DH)
#define SCL2 0.12751744f   // (1/sqrt(128))*log2(e)

__device__ __align__(16) __half g_xh [MTOT*EMB];
__device__ __align__(16) __half g_Wqh[EMB*EMB];
__device__ __align__(16) __half g_Wkh[KVDIM*EMB];
__device__ __align__(16) __half g_Wvh[KVDIM*EMB];
__device__ __align__(16) __half g_Woh[EMB*EMB];
__device__ __align__(16) __half g_Qh [MTOT*EMB];
__device__ __align__(16) __half g_Kh [MTOT*KVDIM];
__device__ __align__(16) __half g_Vh [MTOT*KVDIM];
__device__ __align__(16) __half g_Oh [MTOT*EMB];

__device__ __forceinline__ void mma16(float c[4], uint32_t a0, uint32_t a1,
                                      uint32_t a2, uint32_t a3, uint32_t b0, uint32_t b1) {
    asm volatile("mma.sync.aligned.m16n8k16.row.col.f32.f16.f16.f32 "
                 "{%0,%1,%2,%3}, {%4,%5,%6,%7}, {%8,%9}, {%0,%1,%2,%3};"
                 : "+f"(c[0]), "+f"(c[1]), "+f"(c[2]), "+f"(c[3])
                 : "r"(a0), "r"(a1), "r"(a2), "r"(a3), "r"(b0), "r"(b1));
}
__device__ __forceinline__ void ldsm4(uint32_t& r0, uint32_t& r1, uint32_t& r2,
                                      uint32_t& r3, uint32_t a) {
    asm volatile("ldmatrix.sync.aligned.m8n8.x4.shared.b16 {%0,%1,%2,%3}, [%4];"
                 : "=r"(r0), "=r"(r1), "=r"(r2), "=r"(r3) : "r"(a));
}
__device__ __forceinline__ void ldsm4t(uint32_t& r0, uint32_t& r1, uint32_t& r2,
                                       uint32_t& r3, uint32_t a) {
    asm volatile("ldmatrix.sync.aligned.m8n8.x4.trans.shared.b16 {%0,%1,%2,%3}, [%4];"
                 : "=r"(r0), "=r"(r1), "=r"(r2), "=r"(r3) : "r"(a));
}
__device__ __forceinline__ void cpa16(uint32_t dst, const void* src) {
    asm volatile("cp.async.cg.shared.global [%0], [%1], 16;" :: "r"(dst), "l"(src));
}
#define CP_COMMIT asm volatile("cp.async.commit_group;")
#define CP_WAIT0  asm volatile("cp.async.wait_group 0;")
#define CP_WAIT1  asm volatile("cp.async.wait_group 1;")

__device__ __forceinline__ float ex2f(float x) {
    float y; asm("ex2.approx.ftz.f32 %0, %1;" : "=f"(y) : "f"(x)); return y;
}
__device__ __forceinline__ uint32_t pack2(float a, float b) {
    __half2 h = __floats2half2_rn(a, b); return *reinterpret_cast<uint32_t*>(&h);
}
__device__ __forceinline__ void st2(__half* C, size_t off, float a, float b) {
    *(__half2*)(C + off) = __floats2half2_rn(a, b);
}
__device__ __forceinline__ void st2(float* C, size_t off, float a, float b) {
    *(float2*)(C + off) = make_float2(a, b);
}

__global__ void f32to16(const float4* __restrict__ in, uint2* __restrict__ out, int n4) {
    int i = blockIdx.x * 256 + threadIdx.x;
    if (i < n4) {
        float4 v = in[i];
        __half2 a = __floats2half2_rn(v.x, v.y);
        __half2 b = __floats2half2_rn(v.z, v.w);
        uint2 u;
        u.x = *reinterpret_cast<uint32_t*>(&a);
        u.y = *reinterpret_cast<uint32_t*>(&b);
        out[i] = u;
    }
}

// ---------------- FP16 GEMM: C = A[M,K] @ W[N,K]^T, fp32 acc ----------------
// 128x128 tile, BK=32, 8 warps (2x4), warp tile 64x32, cp.async double buffer.
#define APAD 40
#define GBUFB (128*APAD*2)
#define GSTRIDE (2*GBUFB)

template<typename OutT>
__global__ __launch_bounds__(256, 2)
void gemm16(const __half* __restrict__ A, const __half* __restrict__ W,
            OutT* __restrict__ C, int M, int N, int K) {
    __shared__ __align__(16) __half sAll[2 * 2 * 128 * APAD];

    const int tid = threadIdx.x, lane = tid & 31, wrp = tid >> 5;
    const int g = lane >> 2, q = lane & 3;
    const int wm = wrp >> 2, wn = wrp & 3;
    const int bm = blockIdx.y * 128, bn = blockIdx.x * 128;

    const uint32_t base = (uint32_t)__cvta_generic_to_shared(sAll);
    const uint32_t rAoff = (uint32_t)(((((lane >> 3) & 1) * 8 + (lane & 7)) * APAD + (lane >> 4) * 8) * 2);
    const uint32_t rWoff = (uint32_t)((((lane >> 4) * 8 + (lane & 7)) * APAD + ((lane >> 3) & 1) * 8) * 2);

    const __half* Ap = A + (size_t)bm * K;
    const __half* Wp = W + (size_t)bn * K;

    float acc[4][4][4];
#pragma unroll
    for (int mt = 0; mt < 4; mt++)
#pragma unroll
        for (int nt = 0; nt < 4; nt++)
#pragma unroll
            for (int e = 0; e < 4; e++) acc[mt][nt][e] = 0.f;

#define GLOAD(K0, BUF) {                                                    \
        uint32_t db = base + (BUF) * GSTRIDE;                               \
        for (int i = 0; i < 2; i++) {                                       \
            int c = tid + 256 * i;                                          \
            int row = c >> 2, kc = (c & 3) * 8;                             \
            uint32_t off = (uint32_t)(row * APAD + kc) * 2;                 \
            cpa16(db + off,         Ap + (size_t)row * K + (K0) + kc);      \
            cpa16(db + GBUFB + off, Wp + (size_t)row * K + (K0) + kc);      \
        } }

    GLOAD(0, 0); CP_COMMIT;
    const int nk = K >> 5;
    for (int kt = 0; kt < nk; kt++) {
        const int cur = kt & 1;
        if (kt + 1 < nk) { GLOAD((kt + 1) * 32, cur ^ 1); CP_COMMIT; CP_WAIT1; }
        else CP_WAIT0;
        __syncthreads();

        const uint32_t aB = base + cur * GSTRIDE, wB = aB + GBUFB;
#pragma unroll
        for (int ks = 0; ks < 2; ks++) {
            uint32_t b0r[4], b1r[4];
            ldsm4(b0r[0], b1r[0], b0r[1], b1r[1],
                  wB + rWoff + (uint32_t)((wn * 32) * APAD + ks * 16) * 2);
            ldsm4(b0r[2], b1r[2], b0r[3], b1r[3],
                  wB + rWoff + (uint32_t)((wn * 32 + 16) * APAD + ks * 16) * 2);
#pragma unroll
            for (int mt = 0; mt < 4; mt++) {
                uint32_t a0, a1, a2, a3;
                ldsm4(a0, a1, a2, a3,
                      aB + rAoff + (uint32_t)((wm * 64 + mt * 16) * APAD + ks * 16) * 2);
#pragma unroll
                for (int nt = 0; nt < 4; nt++)
                    mma16(acc[mt][nt], a0, a1, a2, a3, b0r[nt], b1r[nt]);
            }
        }
        __syncthreads();
    }
#undef GLOAD

#pragma unroll
    for (int mt = 0; mt < 4; mt++) {
        const int row = bm + wm * 64 + mt * 16 + g;
#pragma unroll
        for (int nt = 0; nt < 4; nt++) {
            const int col = bn + wn * 32 + nt * 8 + 2 * q;
            st2(C, (size_t)row * N + col,       acc[mt][nt][0], acc[mt][nt][1]);
            st2(C, (size_t)(row + 8) * N + col, acc[mt][nt][2], acc[mt][nt][3]);
        }
    }
}

// ---------------- FP16 flash attention (causal, GQA) ------------------------
// 8 warps, q-tile 128 (16 rows/warp), k-tile 64, P in registers,
// K/V double-buffered cp.async, V via ldmatrix.trans.
#define DPAD 136
#define KVB  (64*DPAD*2)
#define ATTN_SMEM_BYTES (4*KVB)

__global__ __launch_bounds__(256, 1)
void attn16(const __half* __restrict__ Q, const __half* __restrict__ Kg,
            const __half* __restrict__ Vg, __half* __restrict__ O) {
    const int qt = (gridDim.x - 1) - blockIdx.x;
    const int h  = blockIdx.y;
    const int b  = blockIdx.z;
    const int kvh = h >> 2;

    extern __shared__ __half smh[];
    const uint32_t sb = (uint32_t)__cvta_generic_to_shared(smh);

    const int tid = threadIdx.x, lane = tid & 31, w = tid >> 5;
    const int g = lane >> 2, q = lane & 3;
    const int qrow0 = b * SEQ + qt * 128;

    const uint32_t rKoff = (uint32_t)((((lane >> 4) * 8 + (lane & 7)) * DPAD + ((lane >> 3) & 1) * 8) * 2);
    const uint32_t rVoff = (uint32_t)(((((lane >> 3) & 1) * 8 + (lane & 7)) * DPAD + (lane >> 4) * 8) * 2);

    const __half* kbase = Kg + (size_t)(b * SEQ) * KVDIM + kvh * DH;
    const __half* vbase = Vg + (size_t)(b * SEQ) * KVDIM + kvh * DH;

#define LOADKV(KT, BUF) {                                                   \
        const __half* kp = kbase + (size_t)((KT) * 64) * KVDIM;             \
        const __half* vp = vbase + (size_t)((KT) * 64) * KVDIM;             \
        uint32_t kd = sb + (BUF) * KVB;                                     \
        uint32_t vd = sb + 2 * KVB + (BUF) * KVB;                           \
        for (int i = 0; i < 4; i++) {                                       \
            int c = tid + 256 * i;                                          \
            int row = c >> 4, col = (c & 15) * 8;                           \
            uint32_t off = (uint32_t)(row * DPAD + col) * 2;                \
            cpa16(kd + off, kp + (size_t)row * KVDIM + col);                \
            cpa16(vd + off, vp + (size_t)row * KVDIM + col);                \
        } }

    const int nkt = 2 * qt + 2;
    LOADKV(0, 0); CP_COMMIT;

    uint32_t qa[8][4];
    {
        const __half* qb = Q + (size_t)(qrow0 + w * 16) * EMB + h * DH;
#pragma unroll
        for (int ks = 0; ks < 8; ks++) {
            const int d0 = ks * 16 + 2 * q;
            qa[ks][0] = *(const uint32_t*)(qb + (size_t)g * EMB + d0);
            qa[ks][1] = *(const uint32_t*)(qb + (size_t)(g + 8) * EMB + d0);
            qa[ks][2] = *(const uint32_t*)(qb + (size_t)g * EMB + d0 + 8);
            qa[ks][3] = *(const uint32_t*)(qb + (size_t)(g + 8) * EMB + d0 + 8);
        }
    }

    float o[16][4];
#pragma unroll
    for (int nt = 0; nt < 16; nt++)
#pragma unroll
        for (int e = 0; e < 4; e++) o[nt][e] = 0.f;

    float m0 = -INFINITY, m1 = -INFINITY, l0 = 0.f, l1 = 0.f;
    const int qg0 = qt * 128 + w * 16 + g, qg1 = qg0 + 8;

    for (int kt = 0; kt < nkt; kt++) {
        const int cur = kt & 1;
        if (kt + 1 < nkt) { LOADKV(kt + 1, cur ^ 1); CP_COMMIT; CP_WAIT1; }
        else CP_WAIT0;
        __syncthreads();

        float s[8][4];
#pragma unroll
        for (int nt = 0; nt < 8; nt++)
#pragma unroll
            for (int e = 0; e < 4; e++) s[nt][e] = 0.f;

        const uint32_t kB = sb + cur * KVB;
#pragma unroll
        for (int ks = 0; ks < 8; ks++) {
            uint32_t b0r[8], b1r[8];
#pragma unroll
            for (int ntp = 0; ntp < 4; ntp++)
                ldsm4(b0r[2 * ntp], b1r[2 * ntp], b0r[2 * ntp + 1], b1r[2 * ntp + 1],
                      kB + rKoff + (uint32_t)(ntp * 16 * DPAD + ks * 16) * 2);
#pragma unroll
            for (int nt = 0; nt < 8; nt++)
                mma16(s[nt], qa[ks][0], qa[ks][1], qa[ks][2], qa[ks][3], b0r[nt], b1r[nt]);
        }

        if (kt >= 2 * qt) {
#pragma unroll
            for (int nt = 0; nt < 8; nt++) {
                const int kg = kt * 64 + nt * 8 + 2 * q;
                s[nt][0] = (kg     > qg0) ? -INFINITY : s[nt][0] * SCL2;
                s[nt][1] = (kg + 1 > qg0) ? -INFINITY : s[nt][1] * SCL2;
                s[nt][2] = (kg     > qg1) ? -INFINITY : s[nt][2] * SCL2;
                s[nt][3] = (kg + 1 > qg1) ? -INFINITY : s[nt][3] * SCL2;
            }
        } else {
#pragma unroll
            for (int nt = 0; nt < 8; nt++)
#pragma unroll
                for (int e = 0; e < 4; e++) s[nt][e] *= SCL2;
        }

        float rm0 = -INFINITY, rm1 = -INFINITY;
#pragma unroll
        for (int nt = 0; nt < 8; nt++) {
            rm0 = fmaxf(rm0, fmaxf(s[nt][0], s[nt][1]));
            rm1 = fmaxf(rm1, fmaxf(s[nt][2], s[nt][3]));
        }
        rm0 = fmaxf(rm0, __shfl_xor_sync(0xffffffffu, rm0, 1));
        rm0 = fmaxf(rm0, __shfl_xor_sync(0xffffffffu, rm0, 2));
        rm1 = fmaxf(rm1, __shfl_xor_sync(0xffffffffu, rm1, 1));
        rm1 = fmaxf(rm1, __shfl_xor_sync(0xffffffffu, rm1, 2));

        const float mn0 = fmaxf(m0, rm0), mn1 = fmaxf(m1, rm1);
        const float c0 = ex2f(m0 - mn0), c1 = ex2f(m1 - mn1);
        m0 = mn0; m1 = mn1;

        float rs0 = 0.f, rs1 = 0.f;
#pragma unroll
        for (int nt = 0; nt < 8; nt++) {
            s[nt][0] = ex2f(s[nt][0] - mn0);
            s[nt][1] = ex2f(s[nt][1] - mn0);
            s[nt][2] = ex2f(s[nt][2] - mn1);
            s[nt][3] = ex2f(s[nt][3] - mn1);
            rs0 += s[nt][0] + s[nt][1];
            rs1 += s[nt][2] + s[nt][3];
        }
        rs0 += __shfl_xor_sync(0xffffffffu, rs0, 1);
        rs0 += __shfl_xor_sync(0xffffffffu, rs0, 2);
        rs1 += __shfl_xor_sync(0xffffffffu, rs1, 1);
        rs1 += __shfl_xor_sync(0xffffffffu, rs1, 2);
        l0 = l0 * c0 + rs0;
        l1 = l1 * c1 + rs1;

#pragma unroll
        for (int nt = 0; nt < 16; nt++) {
            o[nt][0] *= c0; o[nt][1] *= c0;
            o[nt][2] *= c1; o[nt][3] *= c1;
        }

        const uint32_t vB = sb + 2 * KVB + cur * KVB;
#pragma unroll
        for (int ks2 = 0; ks2 < 4; ks2++) {
            const uint32_t pa0 = pack2(s[2 * ks2][0],     s[2 * ks2][1]);
            const uint32_t pa1 = pack2(s[2 * ks2][2],     s[2 * ks2][3]);
            const uint32_t pa2 = pack2(s[2 * ks2 + 1][0], s[2 * ks2 + 1][1]);
            const uint32_t pa3 = pack2(s[2 * ks2 + 1][2], s[2 * ks2 + 1][3]);
#pragma unroll
            for (int p4 = 0; p4 < 8; p4++) {
                uint32_t r0, r1, r2, r3;
                ldsm4t(r0, r1, r2, r3,
                       vB + rVoff + (uint32_t)(ks2 * 16 * DPAD + p4 * 16) * 2);
                mma16(o[2 * p4],     pa0, pa1, pa2, pa3, r0, r1);
                mma16(o[2 * p4 + 1], pa0, pa1, pa2, pa3, r2, r3);
            }
        }
        __syncthreads();
    }
#undef LOADKV

    const float inv0 = 1.f / l0, inv1 = 1.f / l1;
    __half* ob = O + (size_t)(qrow0 + w * 16) * EMB + h * DH;
#pragma unroll
    for (int nt = 0; nt < 16; nt++) {
        const int d = nt * 8 + 2 * q;
        *(__half2*)(ob + (size_t)g * EMB + d) =
            __floats2half2_rn(o[nt][0] * inv0, o[nt][1] * inv0);
        *(__half2*)(ob + (size_t)(g + 8) * EMB + d) =
            __floats2half2_rn(o[nt][2] * inv1, o[nt][3] * inv1);
    }
}

// ---------------------------------------------------------------------------
extern "C" void kernel_launch(void* const* d_in, const int* in_sizes, int n_in,
                              void* d_out, int out_size) {
    const float* x  = (const float*)d_in[0];
    const float* Wq = (const float*)d_in[1];
    const float* Wk = (const float*)d_in[2];
    const float* Wv = (const float*)d_in[3];
    const float* Wo = (const float*)d_in[4];
    float* out = (float*)d_out;

    void *xh, *wqh, *wkh, *wvh, *woh, *qh, *kh, *vh, *oh;
    cudaGetSymbolAddress(&xh,  g_xh);
    cudaGetSymbolAddress(&wqh, g_Wqh);
    cudaGetSymbolAddress(&wkh, g_Wkh);
    cudaGetSymbolAddress(&wvh, g_Wvh);
    cudaGetSymbolAddress(&woh, g_Woh);
    cudaGetSymbolAddress(&qh,  g_Qh);
    cudaGetSymbolAddress(&kh,  g_Kh);
    cudaGetSymbolAddress(&vh,  g_Vh);
    cudaGetSymbolAddress(&oh,  g_Oh);

    cudaFuncSetAttribute(attn16, cudaFuncAttributeMaxDynamicSharedMemorySize,
                         ATTN_SMEM_BYTES);

    // fp32 -> fp16 conversions
    f32to16<<<(MTOT*EMB/4 + 255)/256, 256>>>((const float4*)x,  (uint2*)xh,  MTOT*EMB/4);
    f32to16<<<(EMB*EMB/4   + 255)/256, 256>>>((const float4*)Wq, (uint2*)wqh, EMB*EMB/4);
    f32to16<<<(KVDIM*EMB/4 + 255)/256, 256>>>((const float4*)Wk, (uint2*)wkh, KVDIM*EMB/4);
    f32to16<<<(KVDIM*EMB/4 + 255)/256, 256>>>((const float4*)Wv, (uint2*)wvh, KVDIM*EMB/4);
    f32to16<<<(EMB*EMB/4   + 255)/256, 256>>>((const float4*)Wo, (uint2*)woh, EMB*EMB/4);

    dim3 blk(256);
    gemm16<__half><<<dim3(EMB / 128, MTOT / 128), blk>>>(
        (const __half*)xh, (const __half*)wqh, (__half*)qh, MTOT, EMB, EMB);
    gemm16<__half><<<dim3(KVDIM / 128, MTOT / 128), blk>>>(
        (const __half*)xh, (const __half*)wkh, (__half*)kh, MTOT, KVDIM, EMB);
    gemm16<__half><<<dim3(KVDIM / 128, MTOT / 128), blk>>>(
        (const __half*)xh, (const __half*)wvh, (__half*)vh, MTOT, KVDIM, EMB);

    attn16<<<dim3(SEQ / 128, NH, BSZ), blk, ATTN_SMEM_BYTES>>>(
        (const __half*)qh, (const __half*)kh, (const __half*)vh, (__half*)oh);

    gemm16<float><<<dim3(EMB / 128, MTOT / 128), blk>>>(
        (const __half*)oh, (const __half*)woh, out, MTOT, EMB, EMB);
}

// round 8
// speedup vs baseline: 2.1196x; 1.0242x over previous
#include <cuda_runtime.h>
#include <cuda_fp16.h>
#include <math.h>
#include <stdint.h>

#define BSZ 2
#define SEQ 2048
#define EMB 2048
#define NH  16
#define NKV 4
#define DH  128
#define MTOT (BSZ*SEQ)
#define KVDIM (NKV*DH)
#define LDKV  (2*KVDIM)         // fused KV activation row stride (1024)
#define SCL2 0.12751744f        // (1/sqrt(128))*log2(e)

__device__ __align__(16) __half g_xh  [MTOT*EMB];
__device__ __align__(16) __half g_Wqh [EMB*EMB];
__device__ __align__(16) __half g_Wkvh[LDKV*EMB];     // rows 0..511 = Wk, 512..1023 = Wv
__device__ __align__(16) __half g_Woh [EMB*EMB];
__device__ __align__(16) __half g_Qh  [MTOT*EMB];
__device__ __align__(16) __half g_KVh [MTOT*LDKV];    // cols 0..511 = K, 512..1023 = V
__device__ __align__(16) __half g_Oh  [MTOT*EMB];

// ---------------- helpers ---------------------------------------------------
__device__ __forceinline__ void mma16(float c[4], uint32_t a0, uint32_t a1,
                                      uint32_t a2, uint32_t a3, uint32_t b0, uint32_t b1) {
    asm volatile("mma.sync.aligned.m16n8k16.row.col.f32.f16.f16.f32 "
                 "{%0,%1,%2,%3}, {%4,%5,%6,%7}, {%8,%9}, {%0,%1,%2,%3};"
                 : "+f"(c[0]), "+f"(c[1]), "+f"(c[2]), "+f"(c[3])
                 : "r"(a0), "r"(a1), "r"(a2), "r"(a3), "r"(b0), "r"(b1));
}
__device__ __forceinline__ void ldsm4(uint32_t& r0, uint32_t& r1, uint32_t& r2,
                                      uint32_t& r3, uint32_t a) {
    asm volatile("ldmatrix.sync.aligned.m8n8.x4.shared.b16 {%0,%1,%2,%3}, [%4];"
                 : "=r"(r0), "=r"(r1), "=r"(r2), "=r"(r3) : "r"(a));
}
__device__ __forceinline__ void ldsm4t(uint32_t& r0, uint32_t& r1, uint32_t& r2,
                                       uint32_t& r3, uint32_t a) {
    asm volatile("ldmatrix.sync.aligned.m8n8.x4.trans.shared.b16 {%0,%1,%2,%3}, [%4];"
                 : "=r"(r0), "=r"(r1), "=r"(r2), "=r"(r3) : "r"(a));
}
__device__ __forceinline__ void cpa16(uint32_t dst, const void* src) {
    asm volatile("cp.async.cg.shared.global [%0], [%1], 16;" :: "r"(dst), "l"(src));
}
#define CP_COMMIT asm volatile("cp.async.commit_group;")
#define CP_WAIT0  asm volatile("cp.async.wait_group 0;")
#define CP_WAIT1  asm volatile("cp.async.wait_group 1;")

__device__ __forceinline__ float ex2f(float x) {
    float y; asm("ex2.approx.ftz.f32 %0, %1;" : "=f"(y) : "f"(x)); return y;
}
__device__ __forceinline__ uint32_t pack2(float a, float b) {
    __half2 h = __floats2half2_rn(a, b); return *reinterpret_cast<uint32_t*>(&h);
}
__device__ __forceinline__ void st2(__half* C, size_t off, float a, float b) {
    *(__half2*)(C + off) = __floats2half2_rn(a, b);
}
__device__ __forceinline__ void st2(float* C, size_t off, float a, float b) {
    *(float2*)(C + off) = make_float2(a, b);
}

__global__ void f32to16(const float4* __restrict__ in, uint2* __restrict__ out, int n4) {
    int i = blockIdx.x * 256 + threadIdx.x;
    if (i < n4) {
        float4 v = in[i];
        __half2 a = __floats2half2_rn(v.x, v.y);
        __half2 b = __floats2half2_rn(v.z, v.w);
        uint2 u;
        u.x = *reinterpret_cast<uint32_t*>(&a);
        u.y = *reinterpret_cast<uint32_t*>(&b);
        out[i] = u;
    }
}

// ---------------- FP16 GEMM: C = A[M,K] @ W[N,K]^T, fp32 acc ----------------
// (byte-identical to the passing Round-4 kernel)
// 128x128 tile, BK=32, 8 warps (2x4), warp tile 64x32, cp.async double buffer.
#define APAD 40
#define GBUFB (128*APAD*2)        // 10240 bytes per matrix per buffer
#define GSTRIDE (2*GBUFB)         // 20480

template<typename OutT>
__global__ __launch_bounds__(256, 2)
void gemm16(const __half* __restrict__ A, const __half* __restrict__ W,
            OutT* __restrict__ C, int M, int N, int K) {
    __shared__ __align__(16) __half sAll[2 * 2 * 128 * APAD];

    const int tid = threadIdx.x, lane = tid & 31, wrp = tid >> 5;
    const int g = lane >> 2, q = lane & 3;
    const int wm = wrp >> 2, wn = wrp & 3;
    const int bm = blockIdx.y * 128, bn = blockIdx.x * 128;

    const uint32_t base = (uint32_t)__cvta_generic_to_shared(sAll);
    const uint32_t rAoff = (uint32_t)(((((lane >> 3) & 1) * 8 + (lane & 7)) * APAD + (lane >> 4) * 8) * 2);
    const uint32_t rWoff = (uint32_t)((((lane >> 4) * 8 + (lane & 7)) * APAD + ((lane >> 3) & 1) * 8) * 2);

    const __half* Ap = A + (size_t)bm * K;
    const __half* Wp = W + (size_t)bn * K;

    float acc[4][4][4];
#pragma unroll
    for (int mt = 0; mt < 4; mt++)
#pragma unroll
        for (int nt = 0; nt < 4; nt++)
#pragma unroll
            for (int e = 0; e < 4; e++) acc[mt][nt][e] = 0.f;

#define GLOAD(K0, BUF) {                                                    \
        uint32_t db = base + (BUF) * GSTRIDE;                               \
        for (int i = 0; i < 2; i++) {                                       \
            int c = tid + 256 * i;                                          \
            int row = c >> 2, kc = (c & 3) * 8;                             \
            uint32_t off = (uint32_t)(row * APAD + kc) * 2;                 \
            cpa16(db + off,          Ap + (size_t)row * K + (K0) + kc);     \
            cpa16(db + GBUFB + off,  Wp + (size_t)row * K + (K0) + kc);     \
        } }

    GLOAD(0, 0); CP_COMMIT;
    const int nk = K >> 5;
    for (int kt = 0; kt < nk; kt++) {
        const int cur = kt & 1;
        if (kt + 1 < nk) { GLOAD((kt + 1) * 32, cur ^ 1); CP_COMMIT; CP_WAIT1; }
        else CP_WAIT0;
        __syncthreads();

        const uint32_t aB = base + cur * GSTRIDE, wB = aB + GBUFB;
#pragma unroll
        for (int ks = 0; ks < 2; ks++) {
            uint32_t b0r[4], b1r[4];
            ldsm4(b0r[0], b1r[0], b0r[1], b1r[1],
                  wB + rWoff + (uint32_t)((wn * 32) * APAD + ks * 16) * 2);
            ldsm4(b0r[2], b1r[2], b0r[3], b1r[3],
                  wB + rWoff + (uint32_t)((wn * 32 + 16) * APAD + ks * 16) * 2);
#pragma unroll
            for (int mt = 0; mt < 4; mt++) {
                uint32_t a0, a1, a2, a3;
                ldsm4(a0, a1, a2, a3,
                      aB + rAoff + (uint32_t)((wm * 64 + mt * 16) * APAD + ks * 16) * 2);
#pragma unroll
                for (int nt = 0; nt < 4; nt++)
                    mma16(acc[mt][nt], a0, a1, a2, a3, b0r[nt], b1r[nt]);
            }
        }
        __syncthreads();
    }
#undef GLOAD

#pragma unroll
    for (int mt = 0; mt < 4; mt++) {
        const int row = bm + wm * 64 + mt * 16 + g;
#pragma unroll
        for (int nt = 0; nt < 4; nt++) {
            const int col = bn + wn * 32 + nt * 8 + 2 * q;
            st2(C, (size_t)row * N + col,       acc[mt][nt][0], acc[mt][nt][1]);
            st2(C, (size_t)(row + 8) * N + col, acc[mt][nt][2], acc[mt][nt][3]);
        }
    }
}

// ---------------- FP16 flash attention (causal, GQA) ------------------------
// Identical to Round-4 except K/V come from the fused KV buffer (stride 1024).
#define DPAD 136
#define KVB  (64*DPAD*2)
#define ATTN_SMEM_BYTES (4*KVB)

__global__ __launch_bounds__(256, 1)
void attn16(const __half* __restrict__ Q, const __half* __restrict__ KV,
            __half* __restrict__ O) {
    const int qt = (gridDim.x - 1) - blockIdx.x;
    const int h  = blockIdx.y;
    const int b  = blockIdx.z;
    const int kvh = h >> 2;

    extern __shared__ __half smh[];
    const uint32_t sb = (uint32_t)__cvta_generic_to_shared(smh);

    const int tid = threadIdx.x, lane = tid & 31, w = tid >> 5;
    const int g = lane >> 2, q = lane & 3;
    const int qrow0 = b * SEQ + qt * 128;

    const uint32_t rKoff = (uint32_t)((((lane >> 4) * 8 + (lane & 7)) * DPAD + ((lane >> 3) & 1) * 8) * 2);
    const uint32_t rVoff = (uint32_t)(((((lane >> 3) & 1) * 8 + (lane & 7)) * DPAD + (lane >> 4) * 8) * 2);

    const __half* kbase = KV + (size_t)(b * SEQ) * LDKV + kvh * DH;
    const __half* vbase = kbase + KVDIM;

#define LOADKV(KT, BUF) {                                                   \
        const __half* kp = kbase + (size_t)((KT) * 64) * LDKV;              \
        const __half* vp = vbase + (size_t)((KT) * 64) * LDKV;              \
        uint32_t kd = sb + (BUF) * KVB;                                     \
        uint32_t vd = sb + 2 * KVB + (BUF) * KVB;                           \
        for (int i = 0; i < 4; i++) {                                       \
            int c = tid + 256 * i;                                          \
            int row = c >> 4, col = (c & 15) * 8;                           \
            uint32_t off = (uint32_t)(row * DPAD + col) * 2;                \
            cpa16(kd + off, kp + (size_t)row * LDKV + col);                 \
            cpa16(vd + off, vp + (size_t)row * LDKV + col);                 \
        } }

    const int nkt = 2 * qt + 2;
    LOADKV(0, 0); CP_COMMIT;

    uint32_t qa[8][4];
    {
        const __half* qb = Q + (size_t)(qrow0 + w * 16) * EMB + h * DH;
#pragma unroll
        for (int ks = 0; ks < 8; ks++) {
            const int d0 = ks * 16 + 2 * q;
            qa[ks][0] = *(const uint32_t*)(qb + (size_t)g * EMB + d0);
            qa[ks][1] = *(const uint32_t*)(qb + (size_t)(g + 8) * EMB + d0);
            qa[ks][2] = *(const uint32_t*)(qb + (size_t)g * EMB + d0 + 8);
            qa[ks][3] = *(const uint32_t*)(qb + (size_t)(g + 8) * EMB + d0 + 8);
        }
    }

    float o[16][4];
#pragma unroll
    for (int nt = 0; nt < 16; nt++)
#pragma unroll
        for (int e = 0; e < 4; e++) o[nt][e] = 0.f;

    float m0 = -INFINITY, m1 = -INFINITY, l0 = 0.f, l1 = 0.f;
    const int qg0 = qt * 128 + w * 16 + g, qg1 = qg0 + 8;

    for (int kt = 0; kt < nkt; kt++) {
        const int cur = kt & 1;
        if (kt + 1 < nkt) { LOADKV(kt + 1, cur ^ 1); CP_COMMIT; CP_WAIT1; }
        else CP_WAIT0;
        __syncthreads();

        float s[8][4];
#pragma unroll
        for (int nt = 0; nt < 8; nt++)
#pragma unroll
            for (int e = 0; e < 4; e++) s[nt][e] = 0.f;

        const uint32_t kB = sb + cur * KVB;
#pragma unroll
        for (int ks = 0; ks < 8; ks++) {
            uint32_t b0r[8], b1r[8];
#pragma unroll
            for (int ntp = 0; ntp < 4; ntp++)
                ldsm4(b0r[2 * ntp], b1r[2 * ntp], b0r[2 * ntp + 1], b1r[2 * ntp + 1],
                      kB + rKoff + (uint32_t)(ntp * 16 * DPAD + ks * 16) * 2);
#pragma unroll
            for (int nt = 0; nt < 8; nt++)
                mma16(s[nt], qa[ks][0], qa[ks][1], qa[ks][2], qa[ks][3], b0r[nt], b1r[nt]);
        }

        if (kt >= 2 * qt) {
#pragma unroll
            for (int nt = 0; nt < 8; nt++) {
                const int kg = kt * 64 + nt * 8 + 2 * q;
                s[nt][0] = (kg     > qg0) ? -INFINITY : s[nt][0] * SCL2;
                s[nt][1] = (kg + 1 > qg0) ? -INFINITY : s[nt][1] * SCL2;
                s[nt][2] = (kg     > qg1) ? -INFINITY : s[nt][2] * SCL2;
                s[nt][3] = (kg + 1 > qg1) ? -INFINITY : s[nt][3] * SCL2;
            }
        } else {
#pragma unroll
            for (int nt = 0; nt < 8; nt++)
#pragma unroll
                for (int e = 0; e < 4; e++) s[nt][e] *= SCL2;
        }

        float rm0 = -INFINITY, rm1 = -INFINITY;
#pragma unroll
        for (int nt = 0; nt < 8; nt++) {
            rm0 = fmaxf(rm0, fmaxf(s[nt][0], s[nt][1]));
            rm1 = fmaxf(rm1, fmaxf(s[nt][2], s[nt][3]));
        }
        rm0 = fmaxf(rm0, __shfl_xor_sync(0xffffffffu, rm0, 1));
        rm0 = fmaxf(rm0, __shfl_xor_sync(0xffffffffu, rm0, 2));
        rm1 = fmaxf(rm1, __shfl_xor_sync(0xffffffffu, rm1, 1));
        rm1 = fmaxf(rm1, __shfl_xor_sync(0xffffffffu, rm1, 2));

        const float mn0 = fmaxf(m0, rm0), mn1 = fmaxf(m1, rm1);
        const float c0 = ex2f(m0 - mn0), c1 = ex2f(m1 - mn1);
        m0 = mn0; m1 = mn1;

        float rs0 = 0.f, rs1 = 0.f;
#pragma unroll
        for (int nt = 0; nt < 8; nt++) {
            s[nt][0] = ex2f(s[nt][0] - mn0);
            s[nt][1] = ex2f(s[nt][1] - mn0);
            s[nt][2] = ex2f(s[nt][2] - mn1);
            s[nt][3] = ex2f(s[nt][3] - mn1);
            rs0 += s[nt][0] + s[nt][1];
            rs1 += s[nt][2] + s[nt][3];
        }
        rs0 += __shfl_xor_sync(0xffffffffu, rs0, 1);
        rs0 += __shfl_xor_sync(0xffffffffu, rs0, 2);
        rs1 += __shfl_xor_sync(0xffffffffu, rs1, 1);
        rs1 += __shfl_xor_sync(0xffffffffu, rs1, 2);
        l0 = l0 * c0 + rs0;
        l1 = l1 * c1 + rs1;

#pragma unroll
        for (int nt = 0; nt < 16; nt++) {
            o[nt][0] *= c0; o[nt][1] *= c0;
            o[nt][2] *= c1; o[nt][3] *= c1;
        }

        const uint32_t vB = sb + 2 * KVB + cur * KVB;
#pragma unroll
        for (int ks2 = 0; ks2 < 4; ks2++) {
            const uint32_t pa0 = pack2(s[2 * ks2][0],     s[2 * ks2][1]);
            const uint32_t pa1 = pack2(s[2 * ks2][2],     s[2 * ks2][3]);
            const uint32_t pa2 = pack2(s[2 * ks2 + 1][0], s[2 * ks2 + 1][1]);
            const uint32_t pa3 = pack2(s[2 * ks2 + 1][2], s[2 * ks2 + 1][3]);
#pragma unroll
            for (int p4 = 0; p4 < 8; p4++) {
                uint32_t r0, r1, r2, r3;
                ldsm4t(r0, r1, r2, r3,
                       vB + rVoff + (uint32_t)(ks2 * 16 * DPAD + p4 * 16) * 2);
                mma16(o[2 * p4],     pa0, pa1, pa2, pa3, r0, r1);
                mma16(o[2 * p4 + 1], pa0, pa1, pa2, pa3, r2, r3);
            }
        }
        __syncthreads();
    }
#undef LOADKV

    const float inv0 = 1.f / l0, inv1 = 1.f / l1;
    __half* ob = O + (size_t)(qrow0 + w * 16) * EMB + h * DH;
#pragma unroll
    for (int nt = 0; nt < 16; nt++) {
        const int d = nt * 8 + 2 * q;
        *(__half2*)(ob + (size_t)g * EMB + d) =
            __floats2half2_rn(o[nt][0] * inv0, o[nt][1] * inv0);
        *(__half2*)(ob + (size_t)(g + 8) * EMB + d) =
            __floats2half2_rn(o[nt][2] * inv1, o[nt][3] * inv1);
    }
}

// ---------------------------------------------------------------------------
extern "C" void kernel_launch(void* const* d_in, const int* in_sizes, int n_in,
                              void* d_out, int out_size) {
    const float* x  = (const float*)d_in[0];
    const float* Wq = (const float*)d_in[1];
    const float* Wk = (const float*)d_in[2];
    const float* Wv = (const float*)d_in[3];
    const float* Wo = (const float*)d_in[4];
    float* out = (float*)d_out;

    void *xh, *wqh, *wkvh, *woh, *qh, *kvh, *oh;
    cudaGetSymbolAddress(&xh,   g_xh);
    cudaGetSymbolAddress(&wqh,  g_Wqh);
    cudaGetSymbolAddress(&wkvh, g_Wkvh);
    cudaGetSymbolAddress(&woh,  g_Woh);
    cudaGetSymbolAddress(&qh,   g_Qh);
    cudaGetSymbolAddress(&kvh,  g_KVh);
    cudaGetSymbolAddress(&oh,   g_Oh);

    cudaFuncSetAttribute(attn16, cudaFuncAttributeMaxDynamicSharedMemorySize,
                         ATTN_SMEM_BYTES);

    // fp32 -> fp16 conversions (Wk, Wv go into one concatenated buffer)
    f32to16<<<(MTOT*EMB/4 + 255)/256, 256>>>((const float4*)x,  (uint2*)xh,  MTOT*EMB/4);
    f32to16<<<(EMB*EMB/4   + 255)/256, 256>>>((const float4*)Wq, (uint2*)wqh, EMB*EMB/4);
    f32to16<<<(KVDIM*EMB/4 + 255)/256, 256>>>((const float4*)Wk, (uint2*)wkvh, KVDIM*EMB/4);
    f32to16<<<(KVDIM*EMB/4 + 255)/256, 256>>>(
        (const float4*)Wv, (uint2*)((__half*)wkvh + (size_t)KVDIM * EMB), KVDIM*EMB/4);
    f32to16<<<(EMB*EMB/4   + 255)/256, 256>>>((const float4*)Wo, (uint2*)woh, EMB*EMB/4);

    dim3 blk(256);
    // Q projection
    gemm16<__half><<<dim3(EMB / 128, MTOT / 128), blk>>>(
        (const __half*)xh, (const __half*)wqh, (__half*)qh, MTOT, EMB, EMB);
    // Fused K+V projection (N = 1024)
    gemm16<__half><<<dim3(LDKV / 128, MTOT / 128), blk>>>(
        (const __half*)xh, (const __half*)wkvh, (__half*)kvh, MTOT, LDKV, EMB);

    attn16<<<dim3(SEQ / 128, NH, BSZ), blk, ATTN_SMEM_BYTES>>>(
        (const __half*)qh, (const __half*)kvh, (__half*)oh);

    // Output projection
    gemm16<float><<<dim3(EMB / 128, MTOT / 128), blk>>>(
        (const __half*)oh, (const __half*)woh, out, MTOT, EMB, EMB);
}

// round 9
// speedup vs baseline: 2.2733x; 1.0725x over previous
#include <cuda_runtime.h>
#include <cuda_fp16.h>
#include <math.h>
#include <stdint.h>

#define BSZ 2
#define SEQ 2048
#define EMB 2048
#define NH  16
#define NKV 4
#define DH  128
#define MTOT (BSZ*SEQ)
#define KVDIM (NKV*DH)
#define LDKV  (2*KVDIM)         // fused KV activation row stride (1024)
#define SCL2 0.12751744f        // (1/sqrt(128))*log2(e)

__device__ __align__(16) __half g_xh  [MTOT*EMB];
__device__ __align__(16) __half g_Wqh [EMB*EMB];
__device__ __align__(16) __half g_Wkvh[LDKV*EMB];     // rows 0..511 = Wk, 512..1023 = Wv
__device__ __align__(16) __half g_Woh [EMB*EMB];
__device__ __align__(16) __half g_Qh  [MTOT*EMB];
__device__ __align__(16) __half g_KVh [MTOT*LDKV];    // cols 0..511 = K, 512..1023 = V
__device__ __align__(16) __half g_Oh  [MTOT*EMB];

// ---------------- helpers ---------------------------------------------------
__device__ __forceinline__ void mma16(float c[4], uint32_t a0, uint32_t a1,
                                      uint32_t a2, uint32_t a3, uint32_t b0, uint32_t b1) {
    asm volatile("mma.sync.aligned.m16n8k16.row.col.f32.f16.f16.f32 "
                 "{%0,%1,%2,%3}, {%4,%5,%6,%7}, {%8,%9}, {%0,%1,%2,%3};"
                 : "+f"(c[0]), "+f"(c[1]), "+f"(c[2]), "+f"(c[3])
                 : "r"(a0), "r"(a1), "r"(a2), "r"(a3), "r"(b0), "r"(b1));
}
__device__ __forceinline__ void ldsm4(uint32_t& r0, uint32_t& r1, uint32_t& r2,
                                      uint32_t& r3, uint32_t a) {
    asm volatile("ldmatrix.sync.aligned.m8n8.x4.shared.b16 {%0,%1,%2,%3}, [%4];"
                 : "=r"(r0), "=r"(r1), "=r"(r2), "=r"(r3) : "r"(a));
}
__device__ __forceinline__ void ldsm4t(uint32_t& r0, uint32_t& r1, uint32_t& r2,
                                       uint32_t& r3, uint32_t a) {
    asm volatile("ldmatrix.sync.aligned.m8n8.x4.trans.shared.b16 {%0,%1,%2,%3}, [%4];"
                 : "=r"(r0), "=r"(r1), "=r"(r2), "=r"(r3) : "r"(a));
}
__device__ __forceinline__ void cpa16(uint32_t dst, const void* src) {
    asm volatile("cp.async.cg.shared.global [%0], [%1], 16;" :: "r"(dst), "l"(src));
}
#define CP_COMMIT asm volatile("cp.async.commit_group;")
#define CP_WAIT0  asm volatile("cp.async.wait_group 0;")

__device__ __forceinline__ float ex2f(float x) {
    float y; asm("ex2.approx.ftz.f32 %0, %1;" : "=f"(y) : "f"(x)); return y;
}
__device__ __forceinline__ uint32_t pack2(float a, float b) {
    __half2 h = __floats2half2_rn(a, b); return *reinterpret_cast<uint32_t*>(&h);
}
__device__ __forceinline__ void st2(__half* C, size_t off, float a, float b) {
    *(__half2*)(C + off) = __floats2half2_rn(a, b);
}
__device__ __forceinline__ void st2(float* C, size_t off, float a, float b) {
    *(float2*)(C + off) = make_float2(a, b);
}

// ---------------- fused fp32 -> fp16 conversion (one launch) ----------------
// block ranges: x[0,8192) Wq[8192,12288) Wk[12288,13312) Wv[13312,14336) Wo[14336,18432)
#define CVT_BLOCKS 18432
__global__ void f32to16_all(const float* __restrict__ x,  const float* __restrict__ Wq,
                            const float* __restrict__ Wk, const float* __restrict__ Wv,
                            const float* __restrict__ Wo,
                            __half* __restrict__ xh, __half* __restrict__ wqh,
                            __half* __restrict__ wkvh, __half* __restrict__ woh) {
    const int blk = blockIdx.x;
    const float4* in;
    uint2* out;
    int idx;
    if (blk < 8192)        { in = (const float4*)x;  out = (uint2*)xh;  idx = blk * 256 + threadIdx.x; }
    else if (blk < 12288)  { in = (const float4*)Wq; out = (uint2*)wqh; idx = (blk - 8192) * 256 + threadIdx.x; }
    else if (blk < 13312)  { in = (const float4*)Wk; out = (uint2*)wkvh; idx = (blk - 12288) * 256 + threadIdx.x; }
    else if (blk < 14336)  { in = (const float4*)Wv; out = (uint2*)(wkvh + (size_t)KVDIM * EMB); idx = (blk - 13312) * 256 + threadIdx.x; }
    else                   { in = (const float4*)Wo; out = (uint2*)woh; idx = (blk - 14336) * 256 + threadIdx.x; }
    float4 v = in[idx];
    __half2 a = __floats2half2_rn(v.x, v.y);
    __half2 b = __floats2half2_rn(v.z, v.w);
    uint2 u;
    u.x = *reinterpret_cast<uint32_t*>(&a);
    u.y = *reinterpret_cast<uint32_t*>(&b);
    out[idx] = u;
}

// ---------------- FP16 GEMM: C = A[M,K] @ W[N,K]^T, fp32 acc ----------------
// 128x128 tile, BK=32, 8 warps (2x4), warp tile 64x32, cp.async double buffer.
// Single __syncthreads per k-iteration (WAIT0 -> sync -> issue next -> compute).
#define APAD 40
#define GBUFB (128*APAD*2)        // 10240 bytes per matrix per buffer
#define GSTRIDE (2*GBUFB)         // 20480

template<typename OutT>
__global__ __launch_bounds__(256, 2)
void gemm16(const __half* __restrict__ A, const __half* __restrict__ W,
            OutT* __restrict__ C, int M, int N, int K) {
    __shared__ __align__(16) __half sAll[2 * 2 * 128 * APAD];

    const int tid = threadIdx.x, lane = tid & 31, wrp = tid >> 5;
    const int g = lane >> 2, q = lane & 3;
    const int wm = wrp >> 2, wn = wrp & 3;
    const int bm = blockIdx.y * 128, bn = blockIdx.x * 128;

    const uint32_t base = (uint32_t)__cvta_generic_to_shared(sAll);
    const uint32_t rAoff = (uint32_t)(((((lane >> 3) & 1) * 8 + (lane & 7)) * APAD + (lane >> 4) * 8) * 2);
    const uint32_t rWoff = (uint32_t)((((lane >> 4) * 8 + (lane & 7)) * APAD + ((lane >> 3) & 1) * 8) * 2);

    const __half* Ap = A + (size_t)bm * K;
    const __half* Wp = W + (size_t)bn * K;

    float acc[4][4][4];
#pragma unroll
    for (int mt = 0; mt < 4; mt++)
#pragma unroll
        for (int nt = 0; nt < 4; nt++)
#pragma unroll
            for (int e = 0; e < 4; e++) acc[mt][nt][e] = 0.f;

#define GLOAD(K0, BUF) {                                                    \
        uint32_t db = base + (BUF) * GSTRIDE;                               \
        for (int i = 0; i < 2; i++) {                                       \
            int c = tid + 256 * i;                                          \
            int row = c >> 2, kc = (c & 3) * 8;                             \
            uint32_t off = (uint32_t)(row * APAD + kc) * 2;                 \
            cpa16(db + off,          Ap + (size_t)row * K + (K0) + kc);     \
            cpa16(db + GBUFB + off,  Wp + (size_t)row * K + (K0) + kc);     \
        } }

    GLOAD(0, 0); CP_COMMIT;
    const int nk = K >> 5;
    for (int kt = 0; kt < nk; kt++) {
        const int cur = kt & 1;
        CP_WAIT0;             // tile kt resident (only pending group)
        __syncthreads();      // publishes tile kt; certifies alt buffer free
        if (kt + 1 < nk) { GLOAD((kt + 1) * 32, cur ^ 1); CP_COMMIT; }

        const uint32_t aB = base + cur * GSTRIDE, wB = aB + GBUFB;
#pragma unroll
        for (int ks = 0; ks < 2; ks++) {
            uint32_t b0r[4], b1r[4];
            ldsm4(b0r[0], b1r[0], b0r[1], b1r[1],
                  wB + rWoff + (uint32_t)((wn * 32) * APAD + ks * 16) * 2);
            ldsm4(b0r[2], b1r[2], b0r[3], b1r[3],
                  wB + rWoff + (uint32_t)((wn * 32 + 16) * APAD + ks * 16) * 2);
#pragma unroll
            for (int mt = 0; mt < 4; mt++) {
                uint32_t a0, a1, a2, a3;
                ldsm4(a0, a1, a2, a3,
                      aB + rAoff + (uint32_t)((wm * 64 + mt * 16) * APAD + ks * 16) * 2);
#pragma unroll
                for (int nt = 0; nt < 4; nt++)
                    mma16(acc[mt][nt], a0, a1, a2, a3, b0r[nt], b1r[nt]);
            }
        }
    }
#undef GLOAD

#pragma unroll
    for (int mt = 0; mt < 4; mt++) {
        const int row = bm + wm * 64 + mt * 16 + g;
#pragma unroll
        for (int nt = 0; nt < 4; nt++) {
            const int col = bn + wn * 32 + nt * 8 + 2 * q;
            st2(C, (size_t)row * N + col,       acc[mt][nt][0], acc[mt][nt][1]);
            st2(C, (size_t)(row + 8) * N + col, acc[mt][nt][2], acc[mt][nt][3]);
        }
    }
}

// ---------------- FP16 flash attention (causal, GQA) ------------------------
// Single sync per k-tile (WAIT0 -> sync -> issue next -> compute).
#define DPAD 136
#define KVB  (64*DPAD*2)
#define ATTN_SMEM_BYTES (4*KVB)

__global__ __launch_bounds__(256, 1)
void attn16(const __half* __restrict__ Q, const __half* __restrict__ KV,
            __half* __restrict__ O) {
    const int qt = (gridDim.x - 1) - blockIdx.x;
    const int h  = blockIdx.y;
    const int b  = blockIdx.z;
    const int kvh = h >> 2;

    extern __shared__ __half smh[];
    const uint32_t sb = (uint32_t)__cvta_generic_to_shared(smh);

    const int tid = threadIdx.x, lane = tid & 31, w = tid >> 5;
    const int g = lane >> 2, q = lane & 3;
    const int qrow0 = b * SEQ + qt * 128;

    const uint32_t rKoff = (uint32_t)((((lane >> 4) * 8 + (lane & 7)) * DPAD + ((lane >> 3) & 1) * 8) * 2);
    const uint32_t rVoff = (uint32_t)(((((lane >> 3) & 1) * 8 + (lane & 7)) * DPAD + (lane >> 4) * 8) * 2);

    const __half* kbase = KV + (size_t)(b * SEQ) * LDKV + kvh * DH;
    const __half* vbase = kbase + KVDIM;

#define LOADKV(KT, BUF) {                                                   \
        const __half* kp = kbase + (size_t)((KT) * 64) * LDKV;              \
        const __half* vp = vbase + (size_t)((KT) * 64) * LDKV;              \
        uint32_t kd = sb + (BUF) * KVB;                                     \
        uint32_t vd = sb + 2 * KVB + (BUF) * KVB;                           \
        for (int i = 0; i < 4; i++) {                                       \
            int c = tid + 256 * i;                                          \
            int row = c >> 4, col = (c & 15) * 8;                           \
            uint32_t off = (uint32_t)(row * DPAD + col) * 2;                \
            cpa16(kd + off, kp + (size_t)row * LDKV + col);                 \
            cpa16(vd + off, vp + (size_t)row * LDKV + col);                 \
        } }

    const int nkt = 2 * qt + 2;
    LOADKV(0, 0); CP_COMMIT;

    uint32_t qa[8][4];
    {
        const __half* qb = Q + (size_t)(qrow0 + w * 16) * EMB + h * DH;
#pragma unroll
        for (int ks = 0; ks < 8; ks++) {
            const int d0 = ks * 16 + 2 * q;
            qa[ks][0] = *(const uint32_t*)(qb + (size_t)g * EMB + d0);
            qa[ks][1] = *(const uint32_t*)(qb + (size_t)(g + 8) * EMB + d0);
            qa[ks][2] = *(const uint32_t*)(qb + (size_t)g * EMB + d0 + 8);
            qa[ks][3] = *(const uint32_t*)(qb + (size_t)(g + 8) * EMB + d0 + 8);
        }
    }

    float o[16][4];
#pragma unroll
    for (int nt = 0; nt < 16; nt++)
#pragma unroll
        for (int e = 0; e < 4; e++) o[nt][e] = 0.f;

    float m0 = -INFINITY, m1 = -INFINITY, l0 = 0.f, l1 = 0.f;
    const int qg0 = qt * 128 + w * 16 + g, qg1 = qg0 + 8;

    for (int kt = 0; kt < nkt; kt++) {
        const int cur = kt & 1;
        CP_WAIT0;             // tile kt resident
        __syncthreads();      // publish kt; alt buffer free
        if (kt + 1 < nkt) { LOADKV(kt + 1, cur ^ 1); CP_COMMIT; }

        float s[8][4];
#pragma unroll
        for (int nt = 0; nt < 8; nt++)
#pragma unroll
            for (int e = 0; e < 4; e++) s[nt][e] = 0.f;

        const uint32_t kB = sb + cur * KVB;
#pragma unroll
        for (int ks = 0; ks < 8; ks++) {
            uint32_t b0r[8], b1r[8];
#pragma unroll
            for (int ntp = 0; ntp < 4; ntp++)
                ldsm4(b0r[2 * ntp], b1r[2 * ntp], b0r[2 * ntp + 1], b1r[2 * ntp + 1],
                      kB + rKoff + (uint32_t)(ntp * 16 * DPAD + ks * 16) * 2);
#pragma unroll
            for (int nt = 0; nt < 8; nt++)
                mma16(s[nt], qa[ks][0], qa[ks][1], qa[ks][2], qa[ks][3], b0r[nt], b1r[nt]);
        }

        if (kt >= 2 * qt) {
#pragma unroll
            for (int nt = 0; nt < 8; nt++) {
                const int kg = kt * 64 + nt * 8 + 2 * q;
                s[nt][0] = (kg     > qg0) ? -INFINITY : s[nt][0] * SCL2;
                s[nt][1] = (kg + 1 > qg0) ? -INFINITY : s[nt][1] * SCL2;
                s[nt][2] = (kg     > qg1) ? -INFINITY : s[nt][2] * SCL2;
                s[nt][3] = (kg + 1 > qg1) ? -INFINITY : s[nt][3] * SCL2;
            }
        } else {
#pragma unroll
            for (int nt = 0; nt < 8; nt++)
#pragma unroll
                for (int e = 0; e < 4; e++) s[nt][e] *= SCL2;
        }

        float rm0 = -INFINITY, rm1 = -INFINITY;
#pragma unroll
        for (int nt = 0; nt < 8; nt++) {
            rm0 = fmaxf(rm0, fmaxf(s[nt][0], s[nt][1]));
            rm1 = fmaxf(rm1, fmaxf(s[nt][2], s[nt][3]));
        }
        rm0 = fmaxf(rm0, __shfl_xor_sync(0xffffffffu, rm0, 1));
        rm0 = fmaxf(rm0, __shfl_xor_sync(0xffffffffu, rm0, 2));
        rm1 = fmaxf(rm1, __shfl_xor_sync(0xffffffffu, rm1, 1));
        rm1 = fmaxf(rm1, __shfl_xor_sync(0xffffffffu, rm1, 2));

        const float mn0 = fmaxf(m0, rm0), mn1 = fmaxf(m1, rm1);
        const float c0 = ex2f(m0 - mn0), c1 = ex2f(m1 - mn1);
        m0 = mn0; m1 = mn1;

        float rs0 = 0.f, rs1 = 0.f;
#pragma unroll
        for (int nt = 0; nt < 8; nt++) {
            s[nt][0] = ex2f(s[nt][0] - mn0);
            s[nt][1] = ex2f(s[nt][1] - mn0);
            s[nt][2] = ex2f(s[nt][2] - mn1);
            s[nt][3] = ex2f(s[nt][3] - mn1);
            rs0 += s[nt][0] + s[nt][1];
            rs1 += s[nt][2] + s[nt][3];
        }
        rs0 += __shfl_xor_sync(0xffffffffu, rs0, 1);
        rs0 += __shfl_xor_sync(0xffffffffu, rs0, 2);
        rs1 += __shfl_xor_sync(0xffffffffu, rs1, 1);
        rs1 += __shfl_xor_sync(0xffffffffu, rs1, 2);
        l0 = l0 * c0 + rs0;
        l1 = l1 * c1 + rs1;

#pragma unroll
        for (int nt = 0; nt < 16; nt++) {
            o[nt][0] *= c0; o[nt][1] *= c0;
            o[nt][2] *= c1; o[nt][3] *= c1;
        }

        const uint32_t vB = sb + 2 * KVB + cur * KVB;
#pragma unroll
        for (int ks2 = 0; ks2 < 4; ks2++) {
            const uint32_t pa0 = pack2(s[2 * ks2][0],     s[2 * ks2][1]);
            const uint32_t pa1 = pack2(s[2 * ks2][2],     s[2 * ks2][3]);
            const uint32_t pa2 = pack2(s[2 * ks2 + 1][0], s[2 * ks2 + 1][1]);
            const uint32_t pa3 = pack2(s[2 * ks2 + 1][2], s[2 * ks2 + 1][3]);
#pragma unroll
            for (int p4 = 0; p4 < 8; p4++) {
                uint32_t r0, r1, r2, r3;
                ldsm4t(r0, r1, r2, r3,
                       vB + rVoff + (uint32_t)(ks2 * 16 * DPAD + p4 * 16) * 2);
                mma16(o[2 * p4],     pa0, pa1, pa2, pa3, r0, r1);
                mma16(o[2 * p4 + 1], pa0, pa1, pa2, pa3, r2, r3);
            }
        }
    }
#undef LOADKV

    const float inv0 = 1.f / l0, inv1 = 1.f / l1;
    __half* ob = O + (size_t)(qrow0 + w * 16) * EMB + h * DH;
#pragma unroll
    for (int nt = 0; nt < 16; nt++) {
        const int d = nt * 8 + 2 * q;
        *(__half2*)(ob + (size_t)g * EMB + d) =
            __floats2half2_rn(o[nt][0] * inv0, o[nt][1] * inv0);
        *(__half2*)(ob + (size_t)(g + 8) * EMB + d) =
            __floats2half2_rn(o[nt][2] * inv1, o[nt][3] * inv1);
    }
}

// ---------------------------------------------------------------------------
extern "C" void kernel_launch(void* const* d_in, const int* in_sizes, int n_in,
                              void* d_out, int out_size) {
    const float* x  = (const float*)d_in[0];
    const float* Wq = (const float*)d_in[1];
    const float* Wk = (const float*)d_in[2];
    const float* Wv = (const float*)d_in[3];
    const float* Wo = (const float*)d_in[4];
    float* out = (float*)d_out;

    void *xh, *wqh, *wkvh, *woh, *qh, *kvh, *oh;
    cudaGetSymbolAddress(&xh,   g_xh);
    cudaGetSymbolAddress(&wqh,  g_Wqh);
    cudaGetSymbolAddress(&wkvh, g_Wkvh);
    cudaGetSymbolAddress(&woh,  g_Woh);
    cudaGetSymbolAddress(&qh,   g_Qh);
    cudaGetSymbolAddress(&kvh,  g_KVh);
    cudaGetSymbolAddress(&oh,   g_Oh);

    cudaFuncSetAttribute(attn16, cudaFuncAttributeMaxDynamicSharedMemorySize,
                         ATTN_SMEM_BYTES);

    // fused conversions (one launch)
    f32to16_all<<<CVT_BLOCKS, 256>>>(x, Wq, Wk, Wv, Wo,
                                     (__half*)xh, (__half*)wqh,
                                     (__half*)wkvh, (__half*)woh);

    dim3 blk(256);
    // Q projection
    gemm16<__half><<<dim3(EMB / 128, MTOT / 128), blk>>>(
        (const __half*)xh, (const __half*)wqh, (__half*)qh, MTOT, EMB, EMB);
    // Fused K+V projection (N = 1024)
    gemm16<__half><<<dim3(LDKV / 128, MTOT / 128), blk>>>(
        (const __half*)xh, (const __half*)wkvh, (__half*)kvh, MTOT, LDKV, EMB);

    attn16<<<dim3(SEQ / 128, NH, BSZ), blk, ATTN_SMEM_BYTES>>>(
        (const __half*)qh, (const __half*)kvh, (__half*)oh);

    // Output projection
    gemm16<float><<<dim3(EMB / 128, MTOT / 128), blk>>>(
        (const __half*)oh, (const __half*)woh, out, MTOT, EMB, EMB);
}